// round 2
// baseline (speedup 1.0000x reference)
#include <cuda_runtime.h>

// Problem constants (from reference)
#define UPDATE_SIZE 4096
#define BATCH 256
#define NUM_UPD 16
#define SNAP_SIZE (UPDATE_SIZE * NUM_UPD)                   // 65536
#define OUT_SIZE (UPDATE_SIZE * BATCH)                      // 1048576
#define SNAP_LEN (SNAP_SIZE + (BATCH - 1) * UPDATE_SIZE)    // 1110016
#define SNAP_V4 (SNAP_LEN / 4)                              // 277504
#define ZERO_V4 (OUT_SIZE / 4)                              // 262144
#define V4_PER_BLK (UPDATE_SIZE / 4)                        // 1024
#define UPD_ROW_V4 (SNAP_SIZE / 4)                          // 16384
// float4 index in update for step i, snap block b, column r:
//   i*16384 + (b-i)*1024 + r = i*15360 + b*1024 + r
#define I_STRIDE_V4 (UPD_ROW_V4 - V4_PER_BLK)               // 15360

__global__ __launch_bounds__(256, 2) void online_avg_kernel(
    const float4* __restrict__ upd,    // (256, 65536) as float4
    const float4* __restrict__ snap,   // (1110016,) as float4
    const float* __restrict__ idxp,    // (1,)
    float4* __restrict__ out4,
    float* __restrict__ out)
{
    int t = blockIdx.x * blockDim.x + threadIdx.x;

    if (t < SNAP_V4) {
        int b = t >> 10;         // snap block index, 0..270
        int base = t;            // b*1024 + r == t
        float idx0 = __ldg(idxp);

        // ---- Phase 1: front-batched loads (max MLP). Clamp invalid steps to a
        // valid row; those values are discarded by rw=0 in the chain below.
        float4 x[NUM_UPD];
        #pragma unroll
        for (int k = 0; k < NUM_UPD; ++k) {
            int i = b - (NUM_UPD - 1) + k;
            int ii = i < 0 ? 0 : (i > BATCH - 1 ? BATCH - 1 : i);
            x[k] = __ldg(&upd[base + ii * I_STRIDE_V4]);
        }
        float4 s = snap[t];

        // ---- Phase 2: serial 16-deep recurrence.
        #pragma unroll
        for (int k = 0; k < NUM_UPD; ++k) {
            int i = b - (NUM_UPD - 1) + k;
            bool valid = (i >= 0) && (i < BATCH);
            // norm value at this position is exactly k+1
            float wt = fminf((float)(k + 1), idx0 + (float)i + 1.0f);
            float rw = valid ? (1.0f / wt) : 0.0f;
            s.x = fmaf(x[k].x - s.x, rw, s.x);
            s.y = fmaf(x[k].y - s.y, rw, s.y);
            s.z = fmaf(x[k].z - s.z, rw, s.z);
            s.w = fmaf(x[k].w - s.w, rw, s.w);
        }
        // d_out[p] = snap_final[p] for p < SNAP_LEN covers both `output`
        // [0, OUT_SIZE) and new_snapshot's live prefix [OUT_SIZE, SNAP_LEN).
        out4[t] = s;
    } else {
        // Zero-fill role: new_snapshot tail = zeros(OUT_SIZE), plus the scalar.
        int z = t - SNAP_V4;
        if (z < ZERO_V4) {
            out4[SNAP_V4 + z] = make_float4(0.f, 0.f, 0.f, 0.f);
        }
        if (z == 0) {
            out[OUT_SIZE + SNAP_LEN] = __ldg(idxp) + (float)BATCH;
        }
    }
}

extern "C" void kernel_launch(void* const* d_in, const int* in_sizes, int n_in,
                              void* d_out, int out_size)
{
    const float4* upd  = (const float4*)d_in[0];
    const float4* snap = (const float4*)d_in[1];
    const float*  idxp = (const float*)d_in[2];

    float4* out4 = (float4*)d_out;
    float*  out  = (float*)d_out;

    const int total_threads = SNAP_V4 + ZERO_V4;      // 539648
    const int threads = 256;
    const int blocks = (total_threads + threads - 1) / threads;  // 2108

    online_avg_kernel<<<blocks, threads>>>(upd, snap, idxp, out4, out);
}

// round 3
// speedup vs baseline: 1.2413x; 1.2413x over previous
#include <cuda_runtime.h>

// Problem constants (from reference)
#define UPDATE_SIZE 4096
#define BATCH 256
#define NUM_UPD 16
#define SNAP_SIZE (UPDATE_SIZE * NUM_UPD)                   // 65536
#define OUT_SIZE (UPDATE_SIZE * BATCH)                      // 1048576
#define SNAP_LEN (SNAP_SIZE + (BATCH - 1) * UPDATE_SIZE)    // 1110016
#define SNAP_V4 (SNAP_LEN / 4)                              // 277504
#define ZERO_V4 (OUT_SIZE / 4)                              // 262144
#define V4_PER_BLK (UPDATE_SIZE / 4)                        // 1024
#define UPD_ROW_V4 (SNAP_SIZE / 4)                          // 16384
// float4 index in update for step i, snap block b, column r:
//   i*16384 + (b-i)*1024 + r = i*15360 + b*1024 + r = i*15360 + t
#define I_STRIDE_V4 (UPD_ROW_V4 - V4_PER_BLK)               // 15360
#define GRP 4

__global__ __launch_bounds__(256) void online_avg_kernel(
    const float4* __restrict__ upd,    // (256, 65536) as float4
    const float4* __restrict__ snap,   // (1110016,) as float4
    const float* __restrict__ idxp,    // (1,)
    float4* __restrict__ out4,
    float* __restrict__ out)
{
    int t = blockIdx.x * blockDim.x + threadIdx.x;

    if (t < SNAP_V4) {
        int b = t >> 10;                 // snap block index, 0..270
        float idx0 = __ldg(idxp);

        // Clamped row index for step k (loads always in-bounds; invalid steps
        // neutralized by rw = 0 in the recurrence).
        #define ROW(k) \
            ( (b - (NUM_UPD - 1) + (k)) < 0 ? 0 : \
              ((b - (NUM_UPD - 1) + (k)) > (BATCH - 1) ? (BATCH - 1) : (b - (NUM_UPD - 1) + (k))) )

        // ---- Depth-4 ping-pong pipeline: group g+1 loads issue before
        // group g's FMA chain consumes. Keeps 4-8 LDG.128 in flight with
        // only ~2*GRP float4 live -> regs <= ~60 -> full occupancy.
        float4 xa[GRP], xb[GRP];
        #pragma unroll
        for (int j = 0; j < GRP; ++j)
            xa[j] = __ldg(&upd[t + ROW(j) * I_STRIDE_V4]);

        float4 s = snap[t];

        #pragma unroll
        for (int g = 0; g < NUM_UPD / GRP; ++g) {
            if (g < NUM_UPD / GRP - 1) {
                #pragma unroll
                for (int j = 0; j < GRP; ++j)
                    xb[j] = __ldg(&upd[t + ROW((g + 1) * GRP + j) * I_STRIDE_V4]);
            }
            #pragma unroll
            for (int j = 0; j < GRP; ++j) {
                int k = g * GRP + j;
                int i = b - (NUM_UPD - 1) + k;
                bool valid = (i >= 0) && (i < BATCH);
                // norm value at this position is exactly k+1
                float wt = fminf((float)(k + 1), idx0 + (float)i + 1.0f);
                float rw = valid ? (1.0f / wt) : 0.0f;
                s.x = fmaf(xa[j].x - s.x, rw, s.x);
                s.y = fmaf(xa[j].y - s.y, rw, s.y);
                s.z = fmaf(xa[j].z - s.z, rw, s.z);
                s.w = fmaf(xa[j].w - s.w, rw, s.w);
            }
            #pragma unroll
            for (int j = 0; j < GRP; ++j) xa[j] = xb[j];
        }
        #undef ROW

        // d_out[p] = snap_final[p] for p < SNAP_LEN covers both `output`
        // [0, OUT_SIZE) and new_snapshot's live prefix [OUT_SIZE, SNAP_LEN).
        out4[t] = s;
    } else {
        // Zero-fill role: new_snapshot tail = zeros(OUT_SIZE), plus the scalar.
        int z = t - SNAP_V4;
        if (z < ZERO_V4) {
            out4[SNAP_V4 + z] = make_float4(0.f, 0.f, 0.f, 0.f);
        }
        if (z == 0) {
            out[OUT_SIZE + SNAP_LEN] = __ldg(idxp) + (float)BATCH;
        }
    }
}

extern "C" void kernel_launch(void* const* d_in, const int* in_sizes, int n_in,
                              void* d_out, int out_size)
{
    const float4* upd  = (const float4*)d_in[0];
    const float4* snap = (const float4*)d_in[1];
    const float*  idxp = (const float*)d_in[2];

    float4* out4 = (float4*)d_out;
    float*  out  = (float*)d_out;

    const int total_threads = SNAP_V4 + ZERO_V4;      // 539648
    const int threads = 256;
    const int blocks = (total_threads + threads - 1) / threads;  // 2108

    online_avg_kernel<<<blocks, threads>>>(upd, snap, idxp, out4, out);
}

// round 4
// speedup vs baseline: 1.2746x; 1.0269x over previous
#include <cuda_runtime.h>

// Problem constants (from reference)
#define UPDATE_SIZE 4096
#define BATCH 256
#define NUM_UPD 16
#define SNAP_SIZE (UPDATE_SIZE * NUM_UPD)                   // 65536
#define OUT_SIZE (UPDATE_SIZE * BATCH)                      // 1048576
#define SNAP_LEN (SNAP_SIZE + (BATCH - 1) * UPDATE_SIZE)    // 1110016
#define SNAP_V4 (SNAP_LEN / 4)                              // 277504
#define ZERO_V4 (OUT_SIZE / 4)                              // 262144
#define V4_PER_BLK (UPDATE_SIZE / 4)                        // 1024
#define UPD_ROW_V4 (SNAP_SIZE / 4)                          // 16384
// float4 index in update for step i, snap block b, column r:
//   i*16384 + (b-i)*1024 + r = i*15360 + t
#define I_STRIDE_V4 (UPD_ROW_V4 - V4_PER_BLK)               // 15360
#define GRP 4

__global__ __launch_bounds__(256) void online_avg_kernel(
    const float4* __restrict__ upd,    // (256, 65536) as float4
    const float4* __restrict__ snap,   // (1110016,) as float4
    const float* __restrict__ idxp,    // (1,)
    float4* __restrict__ out4,
    float* __restrict__ out)
{
    int t = blockIdx.x * blockDim.x + threadIdx.x;

    if (t < SNAP_V4) {
        int b = t >> 10;                 // snap block index, 0..270
        float idx0 = __ldg(idxp);

        // The earliest contributing step for block b has weight
        // min(1, idx0+i0+1) = 1 whenever b >= 15 and idx0 >= 0; a weight-1
        // step overwrites s with x, so the snapshot value is dead there.
        bool need_snap = (b < NUM_UPD - 1) || (idx0 < 0.0f);
        float4 s = need_snap ? snap[t]
                             : make_float4(0.f, 0.f, 0.f, 0.f);

        #define ROW(k) \
            ( (b - (NUM_UPD - 1) + (k)) < 0 ? 0 : \
              ((b - (NUM_UPD - 1) + (k)) > (BATCH - 1) ? (BATCH - 1) : (b - (NUM_UPD - 1) + (k))) )

        // Depth-4 ping-pong pipeline: group g+1 loads issue before group g's
        // FMA chain consumes -> 4-8 LDG.128 in flight at ~50 regs.
        float4 xa[GRP], xb[GRP];
        #pragma unroll
        for (int j = 0; j < GRP; ++j)
            xa[j] = __ldg(&upd[t + ROW(j) * I_STRIDE_V4]);

        #pragma unroll
        for (int g = 0; g < NUM_UPD / GRP; ++g) {
            if (g < NUM_UPD / GRP - 1) {
                #pragma unroll
                for (int j = 0; j < GRP; ++j)
                    xb[j] = __ldg(&upd[t + ROW((g + 1) * GRP + j) * I_STRIDE_V4]);
            }
            #pragma unroll
            for (int j = 0; j < GRP; ++j) {
                int k = g * GRP + j;
                int i = b - (NUM_UPD - 1) + k;
                bool valid = (i >= 0) && (i < BATCH);
                // norm value at this position is exactly k+1
                float wt = fminf((float)(k + 1), idx0 + (float)i + 1.0f);
                float rw = valid ? (1.0f / wt) : 0.0f;
                s.x = fmaf(xa[j].x - s.x, rw, s.x);
                s.y = fmaf(xa[j].y - s.y, rw, s.y);
                s.z = fmaf(xa[j].z - s.z, rw, s.z);
                s.w = fmaf(xa[j].w - s.w, rw, s.w);
            }
            #pragma unroll
            for (int j = 0; j < GRP; ++j) xa[j] = xb[j];
        }
        #undef ROW

        // d_out[p] = snap_final[p] for p < SNAP_LEN covers both `output`
        // [0, OUT_SIZE) and new_snapshot's live prefix [OUT_SIZE, SNAP_LEN).
        out4[t] = s;
    } else {
        // Zero-fill role: new_snapshot tail = zeros(OUT_SIZE), plus the scalar.
        int z = t - SNAP_V4;
        if (z < ZERO_V4) {
            out4[SNAP_V4 + z] = make_float4(0.f, 0.f, 0.f, 0.f);
        }
        if (z == 0) {
            out[OUT_SIZE + SNAP_LEN] = __ldg(idxp) + (float)BATCH;
        }
    }
}

extern "C" void kernel_launch(void* const* d_in, const int* in_sizes, int n_in,
                              void* d_out, int out_size)
{
    const float4* upd  = (const float4*)d_in[0];
    const float4* snap = (const float4*)d_in[1];
    const float*  idxp = (const float*)d_in[2];

    float4* out4 = (float4*)d_out;
    float*  out  = (float*)d_out;

    const int total_threads = SNAP_V4 + ZERO_V4;      // 539648
    const int threads = 256;
    const int blocks = (total_threads + threads - 1) / threads;  // 2108

    online_avg_kernel<<<blocks, threads>>>(upd, snap, idxp, out4, out);
}